// round 9
// baseline (speedup 1.0000x reference)
#include <cuda_runtime.h>
#include <math.h>

#define BB   1024
#define NN   40
#define ETAD 64
#define KK   32
#define ZDIM 32
#define NA   10
#define NB   5
#define CH   128
#define AH   128
#define BH   64
#define NODES (BB*NN)        /* 40960 */
#define EPB   780            /* C(40,2) edges per batch */
#define ZPAD  36             /* padded row stride (floats), 16B aligned */

/* packed constant block offsets (floats, 16B-aligned segments) */
#define OFF_W1   0            /* NB*BH = 320 */
#define OFF_W2T  320          /* NB*BH = 320 */
#define OFF_B1   640          /* BH = 64     */
#define OFF_WSS  704          /* NB*NB = 25  */
#define OFF_B2   736          /* NB = 5      */
#define PACKN    752

/* ---- scratch (static device memory; allocation-free) ---- */
__device__ __align__(16) float g_s[BB*KK];
__device__ __align__(16) float g_z[NODES*ZDIM];
__device__ __align__(16) float g_wsym[NB*ZDIM*ZDIM];
__device__ __align__(16) float g_pack[PACKN];

/* ---- edge-MLP weights in one constant block (single D2D copy) ---- */
__constant__ __align__(16) float c_pack[PACKN];

/* ---- f32x2 packed helpers (sm_100+) ---- */
__device__ __forceinline__ unsigned long long pk2(float lo, float hi) {
    unsigned long long r;
    asm("mov.b64 %0, {%1, %2};" : "=l"(r) : "f"(lo), "f"(hi));
    return r;
}
__device__ __forceinline__ void upk2(unsigned long long v, float& lo, float& hi) {
    asm("mov.b64 {%0, %1}, %2;" : "=f"(lo), "=f"(hi) : "l"(v));
}
__device__ __forceinline__ unsigned long long fma2(unsigned long long a,
                                                   unsigned long long b,
                                                   unsigned long long c) {
    unsigned long long r;
    asm("fma.rn.f32x2 %0, %1, %2, %3;" : "=l"(r) : "l"(a), "l"(b), "l"(c));
    return r;
}

/* lex-order edge index for pair (i<j) in a batch of NN nodes */
__device__ __forceinline__ int eidx(int i, int j) {
    return i*(2*NN - 1 - i)/2 + (j - i - 1);
}

/* ------- kernel 0: prep — Wsym symmetrize + pack edge-MLP weights ------- */
__global__ void k_prep(const float* __restrict__ bm,
                       const float* __restrict__ bW1, const float* __restrict__ bb1,
                       const float* __restrict__ bW2, const float* __restrict__ bb2,
                       const float* __restrict__ bWs, const float* __restrict__ bbs) {
    int i = blockIdx.x * blockDim.x + threadIdx.x;
    if (i < NB*ZDIM*ZDIM) {
        int t = i / (ZDIM*ZDIM);
        int r = (i / ZDIM) % ZDIM;
        int c = i % ZDIM;
        g_wsym[i] = 0.5f * (bm[t*ZDIM*ZDIM + r*ZDIM + c] +
                            bm[t*ZDIM*ZDIM + c*ZDIM + r]);
    }
    if (i < NB*BH) {
        g_pack[OFF_W1 + i] = bW1[i];
        int t = i >> 6, j = i & 63;
        g_pack[OFF_W2T + i] = bW2[j*NB + t];
    }
    if (i < BH)    g_pack[OFF_B1 + i]  = bb1[i];
    if (i < NB*NB) g_pack[OFF_WSS + i] = bWs[i];
    if (i < NB)    g_pack[OFF_B2 + i]  = bb2[i] + bbs[i];
}

/* -------- kernel 1: per-batch cluster resblock logits s[b,k] -------- */
__global__ void k_cluster(const float* __restrict__ eta,
                          const float* __restrict__ cW1, const float* __restrict__ cb1,
                          const float* __restrict__ cW2, const float* __restrict__ cb2,
                          const float* __restrict__ cWs, const float* __restrict__ cbs) {
    __shared__ float eta_sm[ETAD];
    __shared__ float h_sm[CH];
    int b = blockIdx.x;
    int t = threadIdx.x;
    if (t < ETAD) eta_sm[t] = eta[b*ETAD + t];
    __syncthreads();
    float acc = cb1[t];
    #pragma unroll 16
    for (int e = 0; e < ETAD; e++) acc = fmaf(eta_sm[e], cW1[e*CH + t], acc);
    h_sm[t] = fmaxf(acc, 0.f);
    __syncthreads();
    if (t < KK) {
        float s = cb2[t] + cbs[t];
        #pragma unroll 16
        for (int j = 0; j < CH; j++) s = fmaf(h_sm[j], cW2[j*KK + t], s);
        #pragma unroll 16
        for (int e = 0; e < ETAD; e++) s = fmaf(eta_sm[e], cWs[e*KK + t], s);
        g_s[b*KK + t] = s;
    }
}

/* -------- kernel 2: warp handles 4 nodes; weights reused across nodes -------- */
__global__ __launch_bounds__(256)
void k_node(const float* __restrict__ gum, const float* __restrict__ zn,
            const float* __restrict__ cm,  const float* __restrict__ cls,
            const float* __restrict__ aW1, const float* __restrict__ ab1,
            const float* __restrict__ aW2, const float* __restrict__ ab2,
            const float* __restrict__ aWs, const float* __restrict__ absk,
            float* __restrict__ atom_out) {
    __shared__ float4 w1s4[ZDIM*32];
    __shared__ __align__(16) float aw2t[NA*AH];
    __shared__ __align__(16) float awst[NA*ZDIM];
    __shared__ float4 ab1s4[32];
    __shared__ float  ab2s[NA];
    __shared__ __align__(16) float zsm[8][4][ZDIM];
    __shared__ __align__(16) float hsm[8][4][AH];

    int tid  = threadIdx.x;
    int warp = tid >> 5;
    int lane = tid & 31;

    for (int i = tid; i < ZDIM*32; i += 256) w1s4[i] = ((const float4*)aW1)[i];
    for (int i = tid; i < NA*AH;  i += 256) { int o = i / AH, j = i % AH; aw2t[i] = aW2[j*NA + o]; }
    for (int i = tid; i < NA*ZDIM; i += 256) { int o = i / ZDIM, d = i % ZDIM; awst[i] = aWs[d*NA + o]; }
    if (tid < 32) ab1s4[tid] = ((const float4*)ab1)[tid];
    if (tid < NA) ab2s[tid]  = ab2[tid] + absk[tid];
    __syncthreads();

    int node0 = blockIdx.x * 32 + warp;

    #pragma unroll
    for (int u = 0; u < 4; u++) {
        int node = node0 + u*8;
        int b = (unsigned)node / NN;
        float val = g_s[b*KK + lane] + gum[node*KK + lane];
        int idx = lane;
        #pragma unroll
        for (int off = 16; off; off >>= 1) {
            float ov = __shfl_xor_sync(0xffffffffu, val, off);
            int   oi = __shfl_xor_sync(0xffffffffu, idx, off);
            if (ov > val || (ov == val && oi < idx)) { val = ov; idx = oi; }
        }
        int kmax = idx;
        float ls = cls[kmax*ZDIM + lane];
        float sg = __expf(fminf(fmaxf(ls, -20.f), 30.f));
        float z  = fmaf(zn[node*ZDIM + lane], sg, cm[kmax*ZDIM + lane]);
        g_z[node*ZDIM + lane] = z;
        zsm[warp][u][lane] = z;
    }
    __syncwarp();

    float4 acc0 = ab1s4[lane], acc1 = acc0, acc2 = acc0, acc3 = acc0;
    #pragma unroll
    for (int d = 0; d < ZDIM; d++) {
        float4 w = w1s4[d*32 + lane];
        float z0 = zsm[warp][0][d], z1 = zsm[warp][1][d];
        float z2 = zsm[warp][2][d], z3 = zsm[warp][3][d];
        acc0.x = fmaf(z0, w.x, acc0.x); acc0.y = fmaf(z0, w.y, acc0.y);
        acc0.z = fmaf(z0, w.z, acc0.z); acc0.w = fmaf(z0, w.w, acc0.w);
        acc1.x = fmaf(z1, w.x, acc1.x); acc1.y = fmaf(z1, w.y, acc1.y);
        acc1.z = fmaf(z1, w.z, acc1.z); acc1.w = fmaf(z1, w.w, acc1.w);
        acc2.x = fmaf(z2, w.x, acc2.x); acc2.y = fmaf(z2, w.y, acc2.y);
        acc2.z = fmaf(z2, w.z, acc2.z); acc2.w = fmaf(z2, w.w, acc2.w);
        acc3.x = fmaf(z3, w.x, acc3.x); acc3.y = fmaf(z3, w.y, acc3.y);
        acc3.z = fmaf(z3, w.z, acc3.z); acc3.w = fmaf(z3, w.w, acc3.w);
    }
    #define RELU4(a) { a.x=fmaxf(a.x,0.f); a.y=fmaxf(a.y,0.f); a.z=fmaxf(a.z,0.f); a.w=fmaxf(a.w,0.f); }
    RELU4(acc0) RELU4(acc1) RELU4(acc2) RELU4(acc3)
    reinterpret_cast<float4*>(hsm[warp][0])[lane] = acc0;
    reinterpret_cast<float4*>(hsm[warp][1])[lane] = acc1;
    reinterpret_cast<float4*>(hsm[warp][2])[lane] = acc2;
    reinterpret_cast<float4*>(hsm[warp][3])[lane] = acc3;
    __syncwarp();

    #pragma unroll
    for (int pass = 0; pass < 2; pass++) {
        int q = pass*32 + lane;
        if (q < 40) {
            int u = q / 10, o = q % 10;
            float s = ab2s[o];
            #pragma unroll 8
            for (int j4 = 0; j4 < AH/4; j4++) {
                float4 h = *reinterpret_cast<const float4*>(&hsm[warp][u][j4*4]);
                float4 w = *reinterpret_cast<const float4*>(&aw2t[o*AH + j4*4]);
                s = fmaf(h.x, w.x, fmaf(h.y, w.y, fmaf(h.z, w.z, fmaf(h.w, w.w, s))));
            }
            #pragma unroll
            for (int d4 = 0; d4 < ZDIM/4; d4++) {
                float4 zv = *reinterpret_cast<const float4*>(&zsm[warp][u][d4*4]);
                float4 w  = *reinterpret_cast<const float4*>(&awst[o*ZDIM + d4*4]);
                s = fmaf(zv.x, w.x, fmaf(zv.y, w.y, fmaf(zv.z, w.z, fmaf(zv.w, w.w, s))));
            }
            atom_out[(node0 + u*8)*NA + o] = s;
        }
    }
}

/* -------- kernel 3: edges; (i0,i1|j) tiles, constant weights, f32x2 MLP ---- */
__global__ __launch_bounds__(256, 3)
void k_edge(float* __restrict__ edge_out) {
    __shared__ __align__(16) float zs[NN*ZPAD];
    __shared__ __align__(16) float vs[NB*NN*ZPAD];

    int b   = blockIdx.x;
    int tid = threadIdx.x;

    for (int i = tid; i < NN*8; i += 256) {
        int n = i >> 3, d4 = i & 7;
        *reinterpret_cast<float4*>(&zs[n*ZPAD + d4*4]) =
            reinterpret_cast<const float4*>(g_z)[(size_t)b*NN*8 + i];
    }
    __syncthreads();

    /* v[t][j][d] = sum_c Wsym[t][c][d] * z[j][c] */
    for (int base = 0; base < NN*8; base += 256) {
        int idx = base + tid;
        if (idx < NN*8) {
            int j = idx >> 3, d4 = idx & 7;
            #pragma unroll
            for (int t = 0; t < NB; t++) {
                float4 acc = make_float4(0.f, 0.f, 0.f, 0.f);
                const float4* W = reinterpret_cast<const float4*>(g_wsym) + t*256 + d4;
                #pragma unroll 8
                for (int c = 0; c < ZDIM; c++) {
                    float zc = zs[j*ZPAD + c];
                    float4 w = W[c*8];
                    acc.x = fmaf(zc, w.x, acc.x);
                    acc.y = fmaf(zc, w.y, acc.y);
                    acc.z = fmaf(zc, w.z, acc.z);
                    acc.w = fmaf(zc, w.w, acc.w);
                }
                *reinterpret_cast<float4*>(&vs[t*NN*ZPAD + j*ZPAD + d4*4]) = acc;
            }
        }
    }
    __syncthreads();

    float* outb = edge_out + (size_t)b * EPB * NB;

    for (int w = tid; w < 400; w += 256) {
        int i0, i1, j;
        if (w < 380) {
            int I = (int)(19.5f - sqrtf(380.25f - (float)w));
            if (I > 18) I = 18;
            if (I < 0)  I = 0;
            int c = I*(39 - I);
            if (w < c)  { I--; c = I*(39 - I); }
            else        { int c2 = (I + 1)*(38 - I); if (w >= c2) { I++; c = c2; } }
            j  = 2*I + 2 + (w - c);
            i0 = 2*I; i1 = 2*I + 1;
        } else {
            int I = w - 380;
            i0 = 2*I; i1 = 2*I; j = 2*I + 1;
        }
        int e0 = eidx(i0, j), e1 = eidx(i1, j);

        /* bilinear: v row shared across both edges */
        float bil0[NB], bil1[NB];
        #pragma unroll
        for (int t = 0; t < NB; t++) { bil0[t] = 0.f; bil1[t] = 0.f; }
        #pragma unroll
        for (int d4 = 0; d4 < 8; d4++) {
            float4 z0 = *reinterpret_cast<const float4*>(&zs[i0*ZPAD + d4*4]);
            float4 z1 = *reinterpret_cast<const float4*>(&zs[i1*ZPAD + d4*4]);
            #pragma unroll
            for (int t = 0; t < NB; t++) {
                float4 v = *reinterpret_cast<const float4*>(&vs[t*NN*ZPAD + j*ZPAD + d4*4]);
                bil0[t] = fmaf(z0.w, v.w, fmaf(z0.z, v.z, fmaf(z0.y, v.y, fmaf(z0.x, v.x, bil0[t]))));
                bil1[t] = fmaf(z1.w, v.w, fmaf(z1.z, v.z, fmaf(z1.y, v.y, fmaf(z1.x, v.x, bil1[t]))));
            }
        }

        /* skip path + pack */
        unsigned long long oo0[NB], oo1[NB], bp0[NB], bp1[NB];
        #pragma unroll
        for (int t = 0; t < NB; t++) {
            float base = c_pack[OFF_B2 + t];
            float s0 = base, s1 = base;
            #pragma unroll
            for (int u = 0; u < NB; u++) {
                float wv = c_pack[OFF_WSS + u*NB + t];
                s0 = fmaf(bil0[u], wv, s0);
                s1 = fmaf(bil1[u], wv, s1);
            }
            oo0[t] = pk2(s0, 0.f);
            oo1[t] = pk2(s1, 0.f);
            bp0[t] = pk2(bil0[t], bil0[t]);
            bp1[t] = pk2(bil1[t], bil1[t]);
        }

        /* MLP: hidden pairs, weights via uniform constant loads */
        #pragma unroll 4
        for (int jp = 0; jp < BH/2; jp++) {
            unsigned long long b1p =
                *reinterpret_cast<const unsigned long long*>(&c_pack[OFF_B1 + 2*jp]);
            unsigned long long h0 = b1p, h1 = b1p;
            #pragma unroll
            for (int t = 0; t < NB; t++) {
                unsigned long long w1p =
                    *reinterpret_cast<const unsigned long long*>(&c_pack[OFF_W1 + t*BH + 2*jp]);
                h0 = fma2(bp0[t], w1p, h0);
                h1 = fma2(bp1[t], w1p, h1);
            }
            { float x, y; upk2(h0, x, y); h0 = pk2(fmaxf(x, 0.f), fmaxf(y, 0.f)); }
            { float x, y; upk2(h1, x, y); h1 = pk2(fmaxf(x, 0.f), fmaxf(y, 0.f)); }
            #pragma unroll
            for (int t = 0; t < NB; t++) {
                unsigned long long w2p =
                    *reinterpret_cast<const unsigned long long*>(&c_pack[OFF_W2T + t*BH + 2*jp]);
                oo0[t] = fma2(h0, w2p, oo0[t]);
                oo1[t] = fma2(h1, w2p, oo1[t]);
            }
        }

        /* reduce halves, softmax, store */
        {
            float o[NB];
            #pragma unroll
            for (int t = 0; t < NB; t++) { float x, y; upk2(oo0[t], x, y); o[t] = x + y; }
            float m = o[0];
            #pragma unroll
            for (int t = 1; t < NB; t++) m = fmaxf(m, o[t]);
            float s = 0.f, ex[NB];
            #pragma unroll
            for (int t = 0; t < NB; t++) { ex[t] = __expf(o[t] - m); s += ex[t]; }
            float inv = __fdividef(1.f, s);
            #pragma unroll
            for (int t = 0; t < NB; t++) outb[e0*NB + t] = ex[t] * inv;
        }
        {
            float o[NB];
            #pragma unroll
            for (int t = 0; t < NB; t++) { float x, y; upk2(oo1[t], x, y); o[t] = x + y; }
            float m = o[0];
            #pragma unroll
            for (int t = 1; t < NB; t++) m = fmaxf(m, o[t]);
            float s = 0.f, ex[NB];
            #pragma unroll
            for (int t = 0; t < NB; t++) { ex[t] = __expf(o[t] - m); s += ex[t]; }
            float inv = __fdividef(1.f, s);
            #pragma unroll
            for (int t = 0; t < NB; t++) outb[e1*NB + t] = ex[t] * inv;
        }
    }
}

/* ------------------------- launch ------------------------- */
extern "C" void kernel_launch(void* const* d_in, const int* in_sizes, int n_in,
                              void* d_out, int out_size) {
    const float* eta  = (const float*)d_in[0];
    const float* gum  = (const float*)d_in[1];
    const float* zn   = (const float*)d_in[2];
    const float* cW1  = (const float*)d_in[3];
    const float* cb1  = (const float*)d_in[4];
    const float* cW2  = (const float*)d_in[5];
    const float* cb2  = (const float*)d_in[6];
    const float* cWs  = (const float*)d_in[7];
    const float* cbs  = (const float*)d_in[8];
    const float* cm   = (const float*)d_in[9];
    const float* cls  = (const float*)d_in[10];
    const float* aW1  = (const float*)d_in[11];
    const float* ab1  = (const float*)d_in[12];
    const float* aW2  = (const float*)d_in[13];
    const float* ab2  = (const float*)d_in[14];
    const float* aWs  = (const float*)d_in[15];
    const float* absk = (const float*)d_in[16];
    const float* bm   = (const float*)d_in[17];
    const float* bW1  = (const float*)d_in[18];
    const float* bb1  = (const float*)d_in[19];
    const float* bW2  = (const float*)d_in[20];
    const float* bb2  = (const float*)d_in[21];
    const float* bWs  = (const float*)d_in[22];
    const float* bbs  = (const float*)d_in[23];

    float* atom_out = (float*)d_out;
    float* edge_out = atom_out + (size_t)NODES * NA;

    k_prep<<<(NB*ZDIM*ZDIM + 255)/256, 256>>>(bm, bW1, bb1, bW2, bb2, bWs, bbs);

    void* pack_ptr = nullptr;
    cudaGetSymbolAddress(&pack_ptr, g_pack);
    cudaMemcpyToSymbolAsync(c_pack, pack_ptr, PACKN*sizeof(float), 0,
                            cudaMemcpyDeviceToDevice, 0);

    k_cluster<<<BB, CH>>>(eta, cW1, cb1, cW2, cb2, cWs, cbs);
    k_node   <<<NODES/32, 256>>>(gum, zn, cm, cls, aW1, ab1, aW2, ab2, aWs, absk, atom_out);
    k_edge   <<<BB, 256>>>(edge_out);
}

// round 10
// speedup vs baseline: 1.3227x; 1.3227x over previous
#include <cuda_runtime.h>
#include <math.h>

#define BB   1024
#define NN   40
#define ETAD 64
#define KK   32
#define ZDIM 32
#define NA   10
#define NB   5
#define CH   128
#define AH   128
#define BH   64
#define NODES (BB*NN)        /* 40960 */
#define EPB   780            /* C(40,2) edges per batch */
#define ZPAD  36             /* padded row stride (floats), 16B aligned */

/* ---- scratch (static device memory; allocation-free) ---- */
__device__ __align__(16) float g_s[BB*KK];
__device__ __align__(16) float g_z[NODES*ZDIM];
__device__ __align__(16) float g_wsym[NB*ZDIM*ZDIM];
__device__ __align__(16) float g_w2t[NB*BH];          /* bW2 transposed [t][j] */

/* ---- edge-MLP weights: SEPARATE constant symbols (R7 layout).
   Packing these into one array defeated ptxas's LDCU uniform-promotion
   (LDC GPR-dest floor=8 vs LDCU floor=1) and doubled k_edge. Keep split. ---- */
__constant__ __align__(16) float c_bW1[NB*BH];        /* [t][j] raw            */
__constant__ __align__(16) float c_w2t[NB*BH];        /* transposed [t][j]     */
__constant__ __align__(16) float c_bb1[BH];
__constant__ __align__(16) float c_wss[NB*NB];
__constant__ __align__(16) float c_bb2[NB];
__constant__ __align__(16) float c_bbs[NB];

/* ---- f32x2 packed helpers (sm_100+) ---- */
__device__ __forceinline__ unsigned long long pk2(float lo, float hi) {
    unsigned long long r;
    asm("mov.b64 %0, {%1, %2};" : "=l"(r) : "f"(lo), "f"(hi));
    return r;
}
__device__ __forceinline__ void upk2(unsigned long long v, float& lo, float& hi) {
    asm("mov.b64 {%0, %1}, %2;" : "=f"(lo), "=f"(hi) : "l"(v));
}
__device__ __forceinline__ unsigned long long fma2(unsigned long long a,
                                                   unsigned long long b,
                                                   unsigned long long c) {
    unsigned long long r;
    asm("fma.rn.f32x2 %0, %1, %2, %3;" : "=l"(r) : "l"(a), "l"(b), "l"(c));
    return r;
}

/* lex-order edge index for pair (i<j) in a batch of NN nodes */
__device__ __forceinline__ int eidx(int i, int j) {
    return i*(2*NN - 1 - i)/2 + (j - i - 1);
}

/* -------- kernel 0: fused prep + per-batch cluster logits --------
   blocks 0..BB-1: cluster resblock for batch b (128 threads all used)
   blocks BB..BB+19: Wsym symmetrize + bW2 transpose (strided loops)  */
__global__ void k_prep_cluster(const float* __restrict__ bm, const float* __restrict__ bW2,
                               const float* __restrict__ eta,
                               const float* __restrict__ cW1, const float* __restrict__ cb1,
                               const float* __restrict__ cW2, const float* __restrict__ cb2,
                               const float* __restrict__ cWs, const float* __restrict__ cbs) {
    if (blockIdx.x >= BB) {
        int base = (blockIdx.x - BB) * CH;
        for (int i = base + threadIdx.x; i < NB*ZDIM*ZDIM; i += 20*CH) {
            int t = i / (ZDIM*ZDIM);
            int r = (i / ZDIM) % ZDIM;
            int c = i % ZDIM;
            g_wsym[i] = 0.5f * (bm[t*ZDIM*ZDIM + r*ZDIM + c] +
                                bm[t*ZDIM*ZDIM + c*ZDIM + r]);
        }
        for (int i = base + threadIdx.x; i < NB*BH; i += 20*CH) {
            int t = i >> 6, j = i & 63;
            g_w2t[i] = bW2[j*NB + t];
        }
        return;
    }
    __shared__ float eta_sm[ETAD];
    __shared__ float h_sm[CH];
    int b = blockIdx.x;
    int t = threadIdx.x;
    if (t < ETAD) eta_sm[t] = eta[b*ETAD + t];
    __syncthreads();
    float acc = cb1[t];
    #pragma unroll 16
    for (int e = 0; e < ETAD; e++) acc = fmaf(eta_sm[e], cW1[e*CH + t], acc);
    h_sm[t] = fmaxf(acc, 0.f);
    __syncthreads();
    if (t < KK) {
        float s = cb2[t] + cbs[t];
        #pragma unroll 16
        for (int j = 0; j < CH; j++) s = fmaf(h_sm[j], cW2[j*KK + t], s);
        #pragma unroll 16
        for (int e = 0; e < ETAD; e++) s = fmaf(eta_sm[e], cWs[e*KK + t], s);
        g_s[b*KK + t] = s;
    }
}

/* -------- kernel 1: warp handles 4 nodes; weights reused across nodes -------- */
__global__ __launch_bounds__(256)
void k_node(const float* __restrict__ gum, const float* __restrict__ zn,
            const float* __restrict__ cm,  const float* __restrict__ cls,
            const float* __restrict__ aW1, const float* __restrict__ ab1,
            const float* __restrict__ aW2, const float* __restrict__ ab2,
            const float* __restrict__ aWs, const float* __restrict__ absk,
            float* __restrict__ atom_out) {
    __shared__ float4 w1s4[ZDIM*32];
    __shared__ __align__(16) float aw2t[NA*AH];
    __shared__ __align__(16) float awst[NA*ZDIM];
    __shared__ float4 ab1s4[32];
    __shared__ float  ab2s[NA];
    __shared__ __align__(16) float zsm[8][4][ZDIM];
    __shared__ __align__(16) float hsm[8][4][AH];

    int tid  = threadIdx.x;
    int warp = tid >> 5;
    int lane = tid & 31;

    for (int i = tid; i < ZDIM*32; i += 256) w1s4[i] = ((const float4*)aW1)[i];
    for (int i = tid; i < NA*AH;  i += 256) { int o = i / AH, j = i % AH; aw2t[i] = aW2[j*NA + o]; }
    for (int i = tid; i < NA*ZDIM; i += 256) { int o = i / ZDIM, d = i % ZDIM; awst[i] = aWs[d*NA + o]; }
    if (tid < 32) ab1s4[tid] = ((const float4*)ab1)[tid];
    if (tid < NA) ab2s[tid]  = ab2[tid] + absk[tid];
    __syncthreads();

    int node0 = blockIdx.x * 32 + warp;

    #pragma unroll
    for (int u = 0; u < 4; u++) {
        int node = node0 + u*8;
        int b = (unsigned)node / NN;
        float val = g_s[b*KK + lane] + gum[node*KK + lane];
        int idx = lane;
        #pragma unroll
        for (int off = 16; off; off >>= 1) {
            float ov = __shfl_xor_sync(0xffffffffu, val, off);
            int   oi = __shfl_xor_sync(0xffffffffu, idx, off);
            if (ov > val || (ov == val && oi < idx)) { val = ov; idx = oi; }
        }
        int kmax = idx;
        float ls = cls[kmax*ZDIM + lane];
        float sg = __expf(fminf(fmaxf(ls, -20.f), 30.f));
        float z  = fmaf(zn[node*ZDIM + lane], sg, cm[kmax*ZDIM + lane]);
        g_z[node*ZDIM + lane] = z;
        zsm[warp][u][lane] = z;
    }
    __syncwarp();

    float4 acc0 = ab1s4[lane], acc1 = acc0, acc2 = acc0, acc3 = acc0;
    #pragma unroll
    for (int d = 0; d < ZDIM; d++) {
        float4 w = w1s4[d*32 + lane];
        float z0 = zsm[warp][0][d], z1 = zsm[warp][1][d];
        float z2 = zsm[warp][2][d], z3 = zsm[warp][3][d];
        acc0.x = fmaf(z0, w.x, acc0.x); acc0.y = fmaf(z0, w.y, acc0.y);
        acc0.z = fmaf(z0, w.z, acc0.z); acc0.w = fmaf(z0, w.w, acc0.w);
        acc1.x = fmaf(z1, w.x, acc1.x); acc1.y = fmaf(z1, w.y, acc1.y);
        acc1.z = fmaf(z1, w.z, acc1.z); acc1.w = fmaf(z1, w.w, acc1.w);
        acc2.x = fmaf(z2, w.x, acc2.x); acc2.y = fmaf(z2, w.y, acc2.y);
        acc2.z = fmaf(z2, w.z, acc2.z); acc2.w = fmaf(z2, w.w, acc2.w);
        acc3.x = fmaf(z3, w.x, acc3.x); acc3.y = fmaf(z3, w.y, acc3.y);
        acc3.z = fmaf(z3, w.z, acc3.z); acc3.w = fmaf(z3, w.w, acc3.w);
    }
    #define RELU4(a) { a.x=fmaxf(a.x,0.f); a.y=fmaxf(a.y,0.f); a.z=fmaxf(a.z,0.f); a.w=fmaxf(a.w,0.f); }
    RELU4(acc0) RELU4(acc1) RELU4(acc2) RELU4(acc3)
    reinterpret_cast<float4*>(hsm[warp][0])[lane] = acc0;
    reinterpret_cast<float4*>(hsm[warp][1])[lane] = acc1;
    reinterpret_cast<float4*>(hsm[warp][2])[lane] = acc2;
    reinterpret_cast<float4*>(hsm[warp][3])[lane] = acc3;
    __syncwarp();

    #pragma unroll
    for (int pass = 0; pass < 2; pass++) {
        int q = pass*32 + lane;
        if (q < 40) {
            int u = q / 10, o = q % 10;
            float s = ab2s[o];
            #pragma unroll 8
            for (int j4 = 0; j4 < AH/4; j4++) {
                float4 h = *reinterpret_cast<const float4*>(&hsm[warp][u][j4*4]);
                float4 w = *reinterpret_cast<const float4*>(&aw2t[o*AH + j4*4]);
                s = fmaf(h.x, w.x, fmaf(h.y, w.y, fmaf(h.z, w.z, fmaf(h.w, w.w, s))));
            }
            #pragma unroll
            for (int d4 = 0; d4 < ZDIM/4; d4++) {
                float4 zv = *reinterpret_cast<const float4*>(&zsm[warp][u][d4*4]);
                float4 w  = *reinterpret_cast<const float4*>(&awst[o*ZDIM + d4*4]);
                s = fmaf(zv.x, w.x, fmaf(zv.y, w.y, fmaf(zv.z, w.z, fmaf(zv.w, w.w, s))));
            }
            atom_out[(node0 + u*8)*NA + o] = s;
        }
    }
}

/* -------- kernel 2: edges; (i0,i1|j) tiles, constant weights, f32x2 MLP ---- */
__global__ __launch_bounds__(256, 3)
void k_edge(float* __restrict__ edge_out) {
    __shared__ __align__(16) float zs[NN*ZPAD];
    __shared__ __align__(16) float vs[NB*NN*ZPAD];

    int b   = blockIdx.x;
    int tid = threadIdx.x;

    for (int i = tid; i < NN*8; i += 256) {
        int n = i >> 3, d4 = i & 7;
        *reinterpret_cast<float4*>(&zs[n*ZPAD + d4*4]) =
            reinterpret_cast<const float4*>(g_z)[(size_t)b*NN*8 + i];
    }
    __syncthreads();

    /* v[t][j][d] = sum_c Wsym[t][c][d] * z[j][c] */
    for (int base = 0; base < NN*8; base += 256) {
        int idx = base + tid;
        if (idx < NN*8) {
            int j = idx >> 3, d4 = idx & 7;
            #pragma unroll
            for (int t = 0; t < NB; t++) {
                float4 acc = make_float4(0.f, 0.f, 0.f, 0.f);
                const float4* W = reinterpret_cast<const float4*>(g_wsym) + t*256 + d4;
                #pragma unroll 8
                for (int c = 0; c < ZDIM; c++) {
                    float zc = zs[j*ZPAD + c];
                    float4 w = W[c*8];
                    acc.x = fmaf(zc, w.x, acc.x);
                    acc.y = fmaf(zc, w.y, acc.y);
                    acc.z = fmaf(zc, w.z, acc.z);
                    acc.w = fmaf(zc, w.w, acc.w);
                }
                *reinterpret_cast<float4*>(&vs[t*NN*ZPAD + j*ZPAD + d4*4]) = acc;
            }
        }
    }
    __syncthreads();

    float* outb = edge_out + (size_t)b * EPB * NB;

    for (int w = tid; w < 400; w += 256) {
        int i0, i1, j;
        if (w < 380) {
            int I = (int)(19.5f - sqrtf(380.25f - (float)w));
            if (I > 18) I = 18;
            if (I < 0)  I = 0;
            int c = I*(39 - I);
            if (w < c)  { I--; c = I*(39 - I); }
            else        { int c2 = (I + 1)*(38 - I); if (w >= c2) { I++; c = c2; } }
            j  = 2*I + 2 + (w - c);
            i0 = 2*I; i1 = 2*I + 1;
        } else {
            int I = w - 380;
            i0 = 2*I; i1 = 2*I; j = 2*I + 1;
        }
        int e0 = eidx(i0, j), e1 = eidx(i1, j);

        /* bilinear: v row shared across both edges */
        float bil0[NB], bil1[NB];
        #pragma unroll
        for (int t = 0; t < NB; t++) { bil0[t] = 0.f; bil1[t] = 0.f; }
        #pragma unroll
        for (int d4 = 0; d4 < 8; d4++) {
            float4 z0 = *reinterpret_cast<const float4*>(&zs[i0*ZPAD + d4*4]);
            float4 z1 = *reinterpret_cast<const float4*>(&zs[i1*ZPAD + d4*4]);
            #pragma unroll
            for (int t = 0; t < NB; t++) {
                float4 v = *reinterpret_cast<const float4*>(&vs[t*NN*ZPAD + j*ZPAD + d4*4]);
                bil0[t] = fmaf(z0.w, v.w, fmaf(z0.z, v.z, fmaf(z0.y, v.y, fmaf(z0.x, v.x, bil0[t]))));
                bil1[t] = fmaf(z1.w, v.w, fmaf(z1.z, v.z, fmaf(z1.y, v.y, fmaf(z1.x, v.x, bil1[t]))));
            }
        }

        /* skip path + pack */
        unsigned long long oo0[NB], oo1[NB], bp0[NB], bp1[NB];
        #pragma unroll
        for (int t = 0; t < NB; t++) {
            float base = c_bb2[t] + c_bbs[t];
            float s0 = base, s1 = base;
            #pragma unroll
            for (int u = 0; u < NB; u++) {
                float wv = c_wss[u*NB + t];
                s0 = fmaf(bil0[u], wv, s0);
                s1 = fmaf(bil1[u], wv, s1);
            }
            oo0[t] = pk2(s0, 0.f);
            oo1[t] = pk2(s1, 0.f);
            bp0[t] = pk2(bil0[t], bil0[t]);
            bp1[t] = pk2(bil1[t], bil1[t]);
        }

        /* MLP: hidden pairs, weights via uniform constant loads */
        #pragma unroll 4
        for (int jp = 0; jp < BH/2; jp++) {
            unsigned long long b1p =
                *reinterpret_cast<const unsigned long long*>(&c_bb1[2*jp]);
            unsigned long long h0 = b1p, h1 = b1p;
            #pragma unroll
            for (int t = 0; t < NB; t++) {
                unsigned long long w1p =
                    *reinterpret_cast<const unsigned long long*>(&c_bW1[t*BH + 2*jp]);
                h0 = fma2(bp0[t], w1p, h0);
                h1 = fma2(bp1[t], w1p, h1);
            }
            { float x, y; upk2(h0, x, y); h0 = pk2(fmaxf(x, 0.f), fmaxf(y, 0.f)); }
            { float x, y; upk2(h1, x, y); h1 = pk2(fmaxf(x, 0.f), fmaxf(y, 0.f)); }
            #pragma unroll
            for (int t = 0; t < NB; t++) {
                unsigned long long w2p =
                    *reinterpret_cast<const unsigned long long*>(&c_w2t[t*BH + 2*jp]);
                oo0[t] = fma2(h0, w2p, oo0[t]);
                oo1[t] = fma2(h1, w2p, oo1[t]);
            }
        }

        /* reduce halves, softmax, store */
        {
            float o[NB];
            #pragma unroll
            for (int t = 0; t < NB; t++) { float x, y; upk2(oo0[t], x, y); o[t] = x + y; }
            float m = o[0];
            #pragma unroll
            for (int t = 1; t < NB; t++) m = fmaxf(m, o[t]);
            float s = 0.f, ex[NB];
            #pragma unroll
            for (int t = 0; t < NB; t++) { ex[t] = __expf(o[t] - m); s += ex[t]; }
            float inv = __fdividef(1.f, s);
            #pragma unroll
            for (int t = 0; t < NB; t++) outb[e0*NB + t] = ex[t] * inv;
        }
        {
            float o[NB];
            #pragma unroll
            for (int t = 0; t < NB; t++) { float x, y; upk2(oo1[t], x, y); o[t] = x + y; }
            float m = o[0];
            #pragma unroll
            for (int t = 1; t < NB; t++) m = fmaxf(m, o[t]);
            float s = 0.f, ex[NB];
            #pragma unroll
            for (int t = 0; t < NB; t++) { ex[t] = __expf(o[t] - m); s += ex[t]; }
            float inv = __fdividef(1.f, s);
            #pragma unroll
            for (int t = 0; t < NB; t++) outb[e1*NB + t] = ex[t] * inv;
        }
    }
}

/* ------------------------- launch ------------------------- */
extern "C" void kernel_launch(void* const* d_in, const int* in_sizes, int n_in,
                              void* d_out, int out_size) {
    const float* eta  = (const float*)d_in[0];
    const float* gum  = (const float*)d_in[1];
    const float* zn   = (const float*)d_in[2];
    const float* cW1  = (const float*)d_in[3];
    const float* cb1  = (const float*)d_in[4];
    const float* cW2  = (const float*)d_in[5];
    const float* cb2  = (const float*)d_in[6];
    const float* cWs  = (const float*)d_in[7];
    const float* cbs  = (const float*)d_in[8];
    const float* cm   = (const float*)d_in[9];
    const float* cls  = (const float*)d_in[10];
    const float* aW1  = (const float*)d_in[11];
    const float* ab1  = (const float*)d_in[12];
    const float* aW2  = (const float*)d_in[13];
    const float* ab2  = (const float*)d_in[14];
    const float* aWs  = (const float*)d_in[15];
    const float* absk = (const float*)d_in[16];
    const float* bm   = (const float*)d_in[17];
    const float* bW1  = (const float*)d_in[18];
    const float* bb1  = (const float*)d_in[19];
    const float* bW2  = (const float*)d_in[20];
    const float* bb2  = (const float*)d_in[21];
    const float* bWs  = (const float*)d_in[22];
    const float* bbs  = (const float*)d_in[23];

    float* atom_out = (float*)d_out;
    float* edge_out = atom_out + (size_t)NODES * NA;

    /* edge-MLP weights -> separate constant symbols (R7-proven fast path) */
    cudaMemcpyToSymbolAsync(c_bW1, bW1, NB*BH*sizeof(float), 0, cudaMemcpyDeviceToDevice, 0);
    cudaMemcpyToSymbolAsync(c_bb1, bb1, BH*sizeof(float),    0, cudaMemcpyDeviceToDevice, 0);
    cudaMemcpyToSymbolAsync(c_wss, bWs, NB*NB*sizeof(float), 0, cudaMemcpyDeviceToDevice, 0);
    cudaMemcpyToSymbolAsync(c_bb2, bb2, NB*sizeof(float),    0, cudaMemcpyDeviceToDevice, 0);
    cudaMemcpyToSymbolAsync(c_bbs, bbs, NB*sizeof(float),    0, cudaMemcpyDeviceToDevice, 0);

    k_prep_cluster<<<BB + 20, CH>>>(bm, bW2, eta, cW1, cb1, cW2, cb2, cWs, cbs);

    void* w2t_ptr = nullptr;
    cudaGetSymbolAddress(&w2t_ptr, g_w2t);
    cudaMemcpyToSymbolAsync(c_w2t, w2t_ptr, NB*BH*sizeof(float), 0, cudaMemcpyDeviceToDevice, 0);

    k_node<<<NODES/32, 256>>>(gum, zn, cm, cls, aW1, ab1, aW2, ab2, aWs, absk, atom_out);
    k_edge<<<BB, 256>>>(edge_out);
}